// round 14
// baseline (speedup 1.0000x reference)
#include <cuda_runtime.h>
#include <cuda_bf16.h>
#include <cuda_fp16.h>
#include <math.h>
#include <stdint.h>

// Problem constants
#define BB 64
#define PP 16
#define TT 256
#define II 256
#define HH 512
#define OO 5
#define KK 4096      // P*I
#define MM 16384     // B*T
#define NT 2048      // 4*H

#define NBLK 128     // persistent recurrence grid (2 groups of 64)
#define LO_SCALE 2048.0f
#define LO_INV   4.8828125e-4f

// ---------------- scratch (device globals) -----------------------------------
__device__ float g_pre[(size_t)TT * 4 * BB * HH];     // [t][gate][b][h]
__device__ __half g_Ah[(size_t)MM * KK];              // fp16 gathered A
__device__ __half g_Bh[(size_t)NT * KK];              // [n][k] fp16 W_x
__device__ __half g_Wcat[(size_t)NT * 1024];          // [h*4+gate][k'] fp16 recurrence W
__device__ float g_h[2][BB * HH];
__device__ float g_c[BB * HH];
__device__ unsigned g_count2[2] = {0, 0};
__device__ unsigned g_gen2[2] = {0, 0};

// ---------------- helpers ----------------------------------------------------
__device__ __forceinline__ uint32_t smem_u32(const void* p) {
    uint32_t a;
    asm("{ .reg .u64 t; cvta.to.shared.u64 t, %1; cvt.u32.u64 %0, t; }" : "=r"(a) : "l"(p));
    return a;
}
__device__ __forceinline__ void cp16(uint32_t dst, const void* src) {
    asm volatile("cp.async.cg.shared.global [%0], [%1], 16;" :: "r"(dst), "l"(src));
}
__device__ __forceinline__ void cp_commit() {
    asm volatile("cp.async.commit_group;" ::: "memory");
}
__device__ __forceinline__ void ldsm4(uint32_t* r, uint32_t addr) {
    asm volatile("ldmatrix.sync.aligned.m8n8.x4.shared.b16 {%0,%1,%2,%3}, [%4];"
                 : "=r"(r[0]), "=r"(r[1]), "=r"(r[2]), "=r"(r[3]) : "r"(addr));
}
__device__ __forceinline__ void ldsm2(uint32_t* r, uint32_t addr) {
    asm volatile("ldmatrix.sync.aligned.m8n8.x2.shared.b16 {%0,%1}, [%2];"
                 : "=r"(r[0]), "=r"(r[1]) : "r"(addr));
}
__device__ __forceinline__ void mma_f16(float* d, const uint32_t* a, const uint32_t* b) {
    asm volatile(
        "mma.sync.aligned.m16n8k16.row.col.f32.f16.f16.f32 "
        "{%0,%1,%2,%3}, {%4,%5,%6,%7}, {%8,%9}, {%0,%1,%2,%3};"
        : "+f"(d[0]), "+f"(d[1]), "+f"(d[2]), "+f"(d[3])
        : "r"(a[0]), "r"(a[1]), "r"(a[2]), "r"(a[3]), "r"(b[0]), "r"(b[1]));
}
__device__ __forceinline__ uint32_t pack_f16(float a, float b) {
    __half2 v = __floats2half2_rn(a, b);
    return *(uint32_t*)&v;
}
#define SW128(o) ((o) ^ (((o) >> 3) & 0x70))

// ---------------- prep A: gather to fp16 -------------------------------------
__global__ void prep_A(const int* __restrict__ x, const float* __restrict__ emb) {
    int v = blockIdx.x * 256 + threadIdx.x;
    int m = v >> 10;
    int k = (v & 1023) << 2;
    int p = k >> 8, i = k & 255;
    int t = m >> 6, b = m & 63;
    int idx = x[(b * PP + p) * TT + t];
    float4 a = make_float4(0.f, 0.f, 0.f, 0.f);
    if (idx != 0) a = *(const float4*)&emb[(size_t)idx * II + i];
    size_t o = (size_t)m * KK + k;
    *(__half2*)(g_Ah + o)     = __floats2half2_rn(a.x, a.y);
    *(__half2*)(g_Ah + o + 2) = __floats2half2_rn(a.z, a.w);
}

// ---------------- prep B: transpose W[k][h] -> B[n][k], fp16 -----------------
__global__ void prep_B(const float* __restrict__ Wf, const float* __restrict__ Wi,
                       const float* __restrict__ Wg, const float* __restrict__ Wo) {
    __shared__ float tile[32][33];
    int k0 = blockIdx.x * 32;
    int n0 = blockIdx.y * 32;
    int gate = n0 >> 9;
    int h0 = n0 & 511;
    const float* W = (gate == 0) ? Wf : (gate == 1) ? Wi : (gate == 2) ? Wg : Wo;
    int tx = threadIdx.x, ty = threadIdx.y;
    tile[ty][tx] = W[(size_t)(k0 + ty) * HH + h0 + tx];
    __syncthreads();
    g_Bh[(size_t)(n0 + ty) * KK + k0 + tx] = __float2half(tile[tx][ty]);
}

// ---------------- prep Wcat: recurrence W fp16, both segments identical ------
__global__ void prep_Wcat(const float* __restrict__ Wf, const float* __restrict__ Wi,
                          const float* __restrict__ Wg, const float* __restrict__ Wo) {
    int idx = blockIdx.x * 256 + threadIdx.x;   // < NT*1024
    int c = idx >> 10;
    int kp = idx & 1023;
    int g = c & 3;
    int h = c >> 2;
    int kk = kp & 511;
    const float* W = (g == 0) ? Wf : (g == 1) ? Wi : (g == 2) ? Wg : Wo;
    g_Wcat[(size_t)c * 1024 + kp] = __float2half(W[(size_t)kk * HH + h]);
}

// ---------------- mma.sync GEMM: pre = A @ B^T + bias (pure fp16) ------------
// K = 4096 as 64 chunks of 64; 3-stage cp.async pipeline.
#define KCH 64
#define ABUF 16384
#define STAGE (2 * ABUF)
#define GEMM_SMEM (3 * STAGE)          // 98304

__global__ void __launch_bounds__(256, 2)
mma_gemm(const float* __restrict__ bfp, const float* __restrict__ bip,
         const float* __restrict__ bgp, const float* __restrict__ bop) {
    extern __shared__ char smc[];
    uint32_t sbase = smem_u32(smc);
    int tid = threadIdx.x;
    int lane = tid & 31;
    int wid = tid >> 5;
    int mt = blockIdx.y;
    int nt = blockIdx.x;
    int warp_m = wid & 3;
    int warp_n = wid >> 2;

    const __half* A = g_Ah + (size_t)(mt * 128) * KK;
    const __half* B = g_Bh + (size_t)(nt * 128) * KK;

    float acc[2][8][4];
    #pragma unroll
    for (int mf = 0; mf < 2; mf++)
        #pragma unroll
        for (int nf = 0; nf < 8; nf++)
            #pragma unroll
            for (int e = 0; e < 4; e++) acc[mf][nf][e] = 0.f;

    auto stage = [&](int it) {
        int c = it;
        uint32_t ab = sbase + (uint32_t)(it % 3) * STAGE;
        uint32_t bb = ab + ABUF;
        #pragma unroll
        for (int i = 0; i < 4; i++) {
            int v = i * 256 + tid;
            int r = v >> 3, q = v & 7;
            uint32_t so = SW128(r * 128 + q * 16);
            cp16(ab + so, A + (size_t)r * KK + c * KCH + q * 8);
            cp16(bb + so, B + (size_t)r * KK + c * KCH + q * 8);
        }
        cp_commit();
    };

    stage(0);
    stage(1);
    for (int it = 0; it < 64; it++) {
        if (it + 2 < 64) {
            stage(it + 2);
            asm volatile("cp.async.wait_group 2;" ::: "memory");
        } else if (it + 1 < 64) {
            asm volatile("cp.async.wait_group 1;" ::: "memory");
        } else {
            asm volatile("cp.async.wait_group 0;" ::: "memory");
        }
        __syncthreads();

        uint32_t aBase = sbase + (uint32_t)(it % 3) * STAGE;
        uint32_t bBase = aBase + ABUF;
        int arow = lane & 15, asel = lane >> 4;
        int bgrp = lane >> 3, brow = lane & 7;
        #pragma unroll
        for (int ks = 0; ks < 4; ks++) {
            uint32_t a[2][4];
            #pragma unroll
            for (int mf = 0; mf < 2; mf++) {
                int row = warp_m * 32 + mf * 16 + arow;
                ldsm4(a[mf], aBase + SW128(row * 128 + ks * 32 + asel * 16));
            }
            uint32_t b[4][4];
            #pragma unroll
            for (int nfp = 0; nfp < 4; nfp++) {
                int n = warp_n * 64 + nfp * 16 + ((bgrp >> 1) << 3) + brow;
                int kb = ks * 32 + ((bgrp & 1) << 4);
                ldsm4(b[nfp], bBase + SW128(n * 128 + kb));
            }
            #pragma unroll
            for (int mf = 0; mf < 2; mf++)
                #pragma unroll
                for (int nf = 0; nf < 8; nf++)
                    mma_f16(acc[mf][nf], a[mf], &b[nf >> 1][(nf & 1) * 2]);
        }
        __syncthreads();
    }

    int gate = nt >> 2;
    int hbase = (nt & 3) * 128;
    const float* bias = (gate == 0) ? bfp : (gate == 1) ? bip : (gate == 2) ? bgp : bop;
    int grp = lane >> 2, qd = lane & 3;
    #pragma unroll
    for (int mf = 0; mf < 2; mf++) {
        int mrow0 = mt * 128 + warp_m * 32 + mf * 16 + grp;
        #pragma unroll
        for (int half = 0; half < 2; half++) {
            int m = mrow0 + half * 8;
            int t = m >> 6, b = m & 63;
            float* dst = g_pre + ((size_t)(t * 4 + gate) * 64 + b) * 512 + hbase;
            #pragma unroll
            for (int nf = 0; nf < 8; nf++) {
                int col = warp_n * 64 + nf * 8 + qd * 2;
                float2 v;
                v.x = acc[mf][nf][half * 2 + 0] + __ldg(&bias[hbase + col]);
                v.y = acc[mf][nf][half * 2 + 1] + __ldg(&bias[hbase + col + 1]);
                *(float2*)(dst + col) = v;
            }
        }
    }
}

// ---------------- persistent LSTM recurrence (fp16 2-term, split barrier) ----
#define RW0 0
#define RA0 65536
#define RG0 131072
#define LSTM_SMEM (131072 + 32 * 33 * 4)

__device__ __forceinline__ void grid_barrier2(int grp) {
    __threadfence();
    __syncthreads();
    if (threadIdx.x == 0) {
        unsigned gen = *((volatile unsigned*)&g_gen2[grp]);
        if (atomicAdd(&g_count2[grp], 1u) == 63) {
            g_count2[grp] = 0;
            __threadfence();
            *((volatile unsigned*)&g_gen2[grp]) = gen + 1;
        } else {
            while (*((volatile unsigned*)&g_gen2[grp]) == gen) { }
        }
    }
    __syncthreads();
}

__global__ void __launch_bounds__(256, 1)
lstm_persist() {
    extern __shared__ char smx[];
    uint32_t sb = smem_u32(smx);
    float* sG = (float*)(smx + RG0);

    int tid = threadIdx.x;
    int bx  = blockIdx.x;
    int lane = tid & 31;
    int wid  = tid >> 5;
    int grp2 = bx >> 6;
    int b0 = grp2 * 32;
    int colgrp = bx & 63;
    int h0 = colgrp * 8;
    int c0 = colgrp * 32;

    for (int v = tid; v < 32 * 128; v += 256) {
        int r = v >> 7;
        int g8 = v & 127;
        uint4 w = *(const uint4*)(g_Wcat + (size_t)(c0 + r) * 1024 + g8 * 8);
        int chunk = g8 >> 3;
        uint32_t off = SW128(r * 128 + (g8 & 7) * 16);
        *(uint4*)(smx + RW0 + chunk * 4096 + off) = w;
    }

    g_h[0][bx * 256 + tid] = 0.f;

    int mhalf = wid & 1;
    int nq = wid >> 1;
    int bl = tid >> 3;
    int phl = tid & 7;
    float c_reg = 0.f;

    grid_barrier2(grp2);

    for (int t = 0; t < TT; t++) {
        const float* hsrc = g_h[t & 1];
        for (int v = tid; v < 2048; v += 256) {
            int r = v >> 6;
            int gq = v & 63;
            int k = gq * 8;
            float4 x0 = __ldcg((const float4*)&hsrc[(b0 + r) * HH + k]);
            float4 x1 = __ldcg((const float4*)&hsrc[(b0 + r) * HH + k + 4]);
            uint4 HI, LO;
            HI.x = pack_f16(x0.x, x0.y); HI.y = pack_f16(x0.z, x0.w);
            HI.z = pack_f16(x1.x, x1.y); HI.w = pack_f16(x1.z, x1.w);
            __half2 h01 = *(__half2*)&HI.x;
            __half2 h23 = *(__half2*)&HI.y;
            __half2 h45 = *(__half2*)&HI.z;
            __half2 h67 = *(__half2*)&HI.w;
            LO.x = pack_f16((x0.x - __half2float(h01.x)) * LO_SCALE,
                            (x0.y - __half2float(h01.y)) * LO_SCALE);
            LO.y = pack_f16((x0.z - __half2float(h23.x)) * LO_SCALE,
                            (x0.w - __half2float(h23.y)) * LO_SCALE);
            LO.z = pack_f16((x1.x - __half2float(h45.x)) * LO_SCALE,
                            (x1.y - __half2float(h45.y)) * LO_SCALE);
            LO.w = pack_f16((x1.z - __half2float(h67.x)) * LO_SCALE,
                            (x1.w - __half2float(h67.y)) * LO_SCALE);
            int chunk = gq >> 3;
            uint32_t off = SW128(r * 128 + (gq & 7) * 16);
            *(uint4*)(smx + RA0 + chunk * 4096 + off) = HI;
            *(uint4*)(smx + RA0 + (chunk + 8) * 4096 + off) = LO;
        }
        const float* pre_t = g_pre + (size_t)t * 4 * BB * HH;
        float pf = __ldcg(&pre_t[((0 * 64) + b0 + bl) * HH + h0 + phl]);
        float pi = __ldcg(&pre_t[((1 * 64) + b0 + bl) * HH + h0 + phl]);
        float pg = __ldcg(&pre_t[((2 * 64) + b0 + bl) * HH + h0 + phl]);
        float po = __ldcg(&pre_t[((3 * 64) + b0 + bl) * HH + h0 + phl]);
        __syncthreads();

        float acc[4] = {0.f, 0.f, 0.f, 0.f};
        int arow = mhalf * 16 + (lane & 15);
        int asel = lane >> 4;
        int ln = lane & 15;
        int brow = nq * 8 + (ln & 7);
        int bsel = (ln >> 3) & 1;
        #pragma unroll 4
        for (int kk16 = 0; kk16 < 32; kk16++) {
            int chunk = kk16 >> 2;
            int kb = (kk16 & 3) * 32;
            uint32_t a[4], b2[2];
            ldsm4(a, sb + RA0 + chunk * 4096 + SW128(arow * 128 + kb + asel * 16));
            ldsm2(b2, sb + RW0 + chunk * 4096 + SW128(brow * 128 + kb + bsel * 16));
            mma_f16(acc, a, b2);
        }
        #pragma unroll
        for (int e = 0; e < 4; e++) acc[e] *= LO_SCALE;
        #pragma unroll 4
        for (int kk16 = 32; kk16 < 64; kk16++) {
            int chunk = kk16 >> 2;
            int wchunk = (kk16 - 32) >> 2;
            int kb = (kk16 & 3) * 32;
            uint32_t a[4], b2[2];
            ldsm4(a, sb + RA0 + chunk * 4096 + SW128(arow * 128 + kb + asel * 16));
            ldsm2(b2, sb + RW0 + wchunk * 4096 + SW128(brow * 128 + kb + bsel * 16));
            mma_f16(acc, a, b2);
        }
        int rw = mhalf * 16 + (lane >> 2);
        int cw = nq * 8 + (lane & 3) * 2;
        sG[rw * 33 + cw]           = acc[0] * LO_INV;
        sG[rw * 33 + cw + 1]       = acc[1] * LO_INV;
        sG[(rw + 8) * 33 + cw]     = acc[2] * LO_INV;
        sG[(rw + 8) * 33 + cw + 1] = acc[3] * LO_INV;
        __syncthreads();

        float gf = pf + sG[bl * 33 + phl * 4 + 0];
        float gi = pi + sG[bl * 33 + phl * 4 + 1];
        float gg = pg + sG[bl * 33 + phl * 4 + 2];
        float go = po + sG[bl * 33 + phl * 4 + 3];
        float f  = 1.f / (1.f + expf(-gf));
        float i  = 1.f / (1.f + expf(-gi));
        float g  = tanhf(gg);
        float o  = 1.f / (1.f + expf(-go));
        c_reg = f * c_reg + i * g;
        float hnew = o * tanhf(c_reg);
        __stcg(&g_h[(t + 1) & 1][(b0 + bl) * HH + h0 + phl], hnew);

        grid_barrier2(grp2);
    }
    g_c[(b0 + bl) * HH + h0 + phl] = c_reg;
}

// ---------------- final: out = h @ W_lin + b_lin; emit (out, h, c) ----------
__global__ void final_k(const float* __restrict__ Wlin, const float* __restrict__ blin,
                        float* __restrict__ out) {
    int b = blockIdx.x;
    int tid = threadIdx.x;
    const float* h = g_h[0];
    const float* c = g_c;

    float* out_h = out + BB * OO;
    float* out_c = out + BB * OO + BB * HH;
    for (int v = tid; v < HH; v += 256) {
        out_h[b * HH + v] = h[b * HH + v];
        out_c[b * HH + v] = c[b * HH + v];
    }
    __shared__ float red[256 * OO];
    float p[OO];
    #pragma unroll
    for (int o = 0; o < OO; o++) p[o] = 0.f;
    for (int k = tid; k < HH; k += 256) {
        float hv = h[b * HH + k];
        #pragma unroll
        for (int o = 0; o < OO; o++) p[o] += hv * Wlin[k * OO + o];
    }
    #pragma unroll
    for (int o = 0; o < OO; o++) red[tid * OO + o] = p[o];
    __syncthreads();
    for (int s = 128; s > 0; s >>= 1) {
        if (tid < s)
            #pragma unroll
            for (int o = 0; o < OO; o++) red[tid * OO + o] += red[(tid + s) * OO + o];
        __syncthreads();
    }
    if (tid < OO) out[b * OO + tid] = red[tid] + blin[tid];
}

// ---------------- host launcher ---------------------------------------------
extern "C" void kernel_launch(void* const* d_in, const int* in_sizes, int n_in,
                              void* d_out, int out_size) {
    const int*   x    = (const int*)d_in[0];
    const float* emb  = (const float*)d_in[1];
    const float* Wfx  = (const float*)d_in[2];
    const float* Wfh  = (const float*)d_in[3];
    const float* bfp  = (const float*)d_in[4];
    const float* Wix  = (const float*)d_in[5];
    const float* Wih  = (const float*)d_in[6];
    const float* bip  = (const float*)d_in[7];
    const float* Wgx  = (const float*)d_in[8];
    const float* Wgh  = (const float*)d_in[9];
    const float* bgp  = (const float*)d_in[10];
    const float* Wox  = (const float*)d_in[11];
    const float* Woh  = (const float*)d_in[12];
    const float* bop  = (const float*)d_in[13];
    const float* Wlin = (const float*)d_in[14];
    const float* blin = (const float*)d_in[15];
    float* out = (float*)d_out;

    cudaFuncSetAttribute(mma_gemm, cudaFuncAttributeMaxDynamicSharedMemorySize, GEMM_SMEM);
    cudaFuncSetAttribute(lstm_persist, cudaFuncAttributeMaxDynamicSharedMemorySize, LSTM_SMEM);

    prep_A<<<65536, 256>>>(x, emb);
    prep_B<<<dim3(KK / 32, NT / 32), dim3(32, 32)>>>(Wfx, Wix, Wgx, Wox);
    prep_Wcat<<<NT * 4, 256>>>(Wfh, Wih, Wgh, Woh);
    mma_gemm<<<dim3(NT / 128, MM / 128), 256, GEMM_SMEM>>>(bfp, bip, bgp, bop);
    lstm_persist<<<NBLK, 256, LSTM_SMEM>>>();
    final_k<<<BB, 256>>>(Wlin, blin, out);
}

// round 16
// speedup vs baseline: 1.5140x; 1.5140x over previous
#include <cuda_runtime.h>
#include <cuda_bf16.h>
#include <cuda_fp16.h>
#include <math.h>
#include <stdint.h>

// Problem constants
#define BB 64
#define PP 16
#define TT 256
#define II 256
#define HH 512
#define OO 5
#define KK 4096      // P*I
#define MM 16384     // B*T
#define NT 2048      // 4*H

#define NBLK 128     // persistent recurrence grid (2 groups of 64)
#define LO_SCALE 2048.0f
#define LO_INV   4.8828125e-4f

// ---------------- scratch (device globals) -----------------------------------
__device__ float g_pre[(size_t)TT * 4 * BB * HH];     // [t][gate][b][h]
__device__ __half g_Ah[(size_t)MM * KK];              // fp16 gathered A
__device__ __half g_Bh[(size_t)NT * KK];              // [n][k] fp16 W_x
__device__ __half g_Wcat[(size_t)NT * 1024];          // [h*4+gate][k'] fp16 recurrence W
__device__ __half g_hHI[2][BB * HH];                  // h hi (fp16), double buffered
__device__ __half g_hLO[2][BB * HH];                  // h lo * 2048 (fp16)
__device__ float g_hfinal[BB * HH];
__device__ float g_c[BB * HH];
__device__ unsigned g_count2[2] = {0, 0};
__device__ unsigned g_gen2[2] = {0, 0};

// ---------------- helpers ----------------------------------------------------
__device__ __forceinline__ uint32_t smem_u32(const void* p) {
    uint32_t a;
    asm("{ .reg .u64 t; cvta.to.shared.u64 t, %1; cvt.u32.u64 %0, t; }" : "=r"(a) : "l"(p));
    return a;
}
__device__ __forceinline__ void cp16(uint32_t dst, const void* src) {
    asm volatile("cp.async.cg.shared.global [%0], [%1], 16;" :: "r"(dst), "l"(src));
}
__device__ __forceinline__ void cp_commit() {
    asm volatile("cp.async.commit_group;" ::: "memory");
}
__device__ __forceinline__ void ldsm4(uint32_t* r, uint32_t addr) {
    asm volatile("ldmatrix.sync.aligned.m8n8.x4.shared.b16 {%0,%1,%2,%3}, [%4];"
                 : "=r"(r[0]), "=r"(r[1]), "=r"(r[2]), "=r"(r[3]) : "r"(addr));
}
__device__ __forceinline__ void ldsm2(uint32_t* r, uint32_t addr) {
    asm volatile("ldmatrix.sync.aligned.m8n8.x2.shared.b16 {%0,%1}, [%2];"
                 : "=r"(r[0]), "=r"(r[1]) : "r"(addr));
}
__device__ __forceinline__ void mma_f16(float* d, const uint32_t* a, const uint32_t* b) {
    asm volatile(
        "mma.sync.aligned.m16n8k16.row.col.f32.f16.f16.f32 "
        "{%0,%1,%2,%3}, {%4,%5,%6,%7}, {%8,%9}, {%0,%1,%2,%3};"
        : "+f"(d[0]), "+f"(d[1]), "+f"(d[2]), "+f"(d[3])
        : "r"(a[0]), "r"(a[1]), "r"(a[2]), "r"(a[3]), "r"(b[0]), "r"(b[1]));
}
__device__ __forceinline__ float sigm_f(float x) {
    return __fdividef(1.f, 1.f + __expf(-x));
}
__device__ __forceinline__ float tanh_f(float x) {
    return 1.f - __fdividef(2.f, __expf(2.f * x) + 1.f);
}
#define SW128(o) ((o) ^ (((o) >> 3) & 0x70))

// ---------------- prep A: gather to fp16 -------------------------------------
__global__ void prep_A(const int* __restrict__ x, const float* __restrict__ emb) {
    int v = blockIdx.x * 256 + threadIdx.x;
    int m = v >> 10;
    int k = (v & 1023) << 2;
    int p = k >> 8, i = k & 255;
    int t = m >> 6, b = m & 63;
    int idx = x[(b * PP + p) * TT + t];
    float4 a = make_float4(0.f, 0.f, 0.f, 0.f);
    if (idx != 0) a = *(const float4*)&emb[(size_t)idx * II + i];
    size_t o = (size_t)m * KK + k;
    *(__half2*)(g_Ah + o)     = __floats2half2_rn(a.x, a.y);
    *(__half2*)(g_Ah + o + 2) = __floats2half2_rn(a.z, a.w);
}

// ---------------- prep B: transpose W[k][h] -> B[n][k], fp16 -----------------
__global__ void prep_B(const float* __restrict__ Wf, const float* __restrict__ Wi,
                       const float* __restrict__ Wg, const float* __restrict__ Wo) {
    __shared__ float tile[32][33];
    int k0 = blockIdx.x * 32;
    int n0 = blockIdx.y * 32;
    int gate = n0 >> 9;
    int h0 = n0 & 511;
    const float* W = (gate == 0) ? Wf : (gate == 1) ? Wi : (gate == 2) ? Wg : Wo;
    int tx = threadIdx.x, ty = threadIdx.y;
    tile[ty][tx] = W[(size_t)(k0 + ty) * HH + h0 + tx];
    __syncthreads();
    g_Bh[(size_t)(n0 + ty) * KK + k0 + tx] = __float2half(tile[tx][ty]);
}

// ---------------- prep Wcat: recurrence W fp16, both segments identical ------
__global__ void prep_Wcat(const float* __restrict__ Wf, const float* __restrict__ Wi,
                          const float* __restrict__ Wg, const float* __restrict__ Wo) {
    int idx = blockIdx.x * 256 + threadIdx.x;   // < NT*1024
    int c = idx >> 10;
    int kp = idx & 1023;
    int g = c & 3;
    int h = c >> 2;
    int kk = kp & 511;
    const float* W = (g == 0) ? Wf : (g == 1) ? Wi : (g == 2) ? Wg : Wo;
    g_Wcat[(size_t)c * 1024 + kp] = __float2half(W[(size_t)kk * HH + h]);
}

// ---------------- mma.sync GEMM: pre = A @ B^T + bias (pure fp16) ------------
#define KCH 64
#define ABUF 16384
#define STAGE (2 * ABUF)
#define GEMM_SMEM (3 * STAGE)          // 98304

__global__ void __launch_bounds__(256, 2)
mma_gemm(const float* __restrict__ bfp, const float* __restrict__ bip,
         const float* __restrict__ bgp, const float* __restrict__ bop) {
    extern __shared__ char smc[];
    uint32_t sbase = smem_u32(smc);
    int tid = threadIdx.x;
    int lane = tid & 31;
    int wid = tid >> 5;
    int mt = blockIdx.y;
    int nt = blockIdx.x;
    int warp_m = wid & 3;
    int warp_n = wid >> 2;

    const __half* A = g_Ah + (size_t)(mt * 128) * KK;
    const __half* B = g_Bh + (size_t)(nt * 128) * KK;

    float acc[2][8][4];
    #pragma unroll
    for (int mf = 0; mf < 2; mf++)
        #pragma unroll
        for (int nf = 0; nf < 8; nf++)
            #pragma unroll
            for (int e = 0; e < 4; e++) acc[mf][nf][e] = 0.f;

    auto stage = [&](int it) {
        int c = it;
        uint32_t ab = sbase + (uint32_t)(it % 3) * STAGE;
        uint32_t bb = ab + ABUF;
        #pragma unroll
        for (int i = 0; i < 4; i++) {
            int v = i * 256 + tid;
            int r = v >> 3, q = v & 7;
            uint32_t so = SW128(r * 128 + q * 16);
            cp16(ab + so, A + (size_t)r * KK + c * KCH + q * 8);
            cp16(bb + so, B + (size_t)r * KK + c * KCH + q * 8);
        }
        cp_commit();
    };

    stage(0);
    stage(1);
    for (int it = 0; it < 64; it++) {
        if (it + 2 < 64) {
            stage(it + 2);
            asm volatile("cp.async.wait_group 2;" ::: "memory");
        } else if (it + 1 < 64) {
            asm volatile("cp.async.wait_group 1;" ::: "memory");
        } else {
            asm volatile("cp.async.wait_group 0;" ::: "memory");
        }
        __syncthreads();

        uint32_t aBase = sbase + (uint32_t)(it % 3) * STAGE;
        uint32_t bBase = aBase + ABUF;
        int arow = lane & 15, asel = lane >> 4;
        int bgrp = lane >> 3, brow = lane & 7;
        #pragma unroll
        for (int ks = 0; ks < 4; ks++) {
            uint32_t a[2][4];
            #pragma unroll
            for (int mf = 0; mf < 2; mf++) {
                int row = warp_m * 32 + mf * 16 + arow;
                ldsm4(a[mf], aBase + SW128(row * 128 + ks * 32 + asel * 16));
            }
            uint32_t b[4][4];
            #pragma unroll
            for (int nfp = 0; nfp < 4; nfp++) {
                int n = warp_n * 64 + nfp * 16 + ((bgrp >> 1) << 3) + brow;
                int kb = ks * 32 + ((bgrp & 1) << 4);
                ldsm4(b[nfp], bBase + SW128(n * 128 + kb));
            }
            #pragma unroll
            for (int mf = 0; mf < 2; mf++)
                #pragma unroll
                for (int nf = 0; nf < 8; nf++)
                    mma_f16(acc[mf][nf], a[mf], &b[nf >> 1][(nf & 1) * 2]);
        }
        __syncthreads();
    }

    int gate = nt >> 2;
    int hbase = (nt & 3) * 128;
    const float* bias = (gate == 0) ? bfp : (gate == 1) ? bip : (gate == 2) ? bgp : bop;
    int grp = lane >> 2, qd = lane & 3;
    #pragma unroll
    for (int mf = 0; mf < 2; mf++) {
        int mrow0 = mt * 128 + warp_m * 32 + mf * 16 + grp;
        #pragma unroll
        for (int half = 0; half < 2; half++) {
            int m = mrow0 + half * 8;
            int t = m >> 6, b = m & 63;
            float* dst = g_pre + ((size_t)(t * 4 + gate) * 64 + b) * 512 + hbase;
            #pragma unroll
            for (int nf = 0; nf < 8; nf++) {
                int col = warp_n * 64 + nf * 8 + qd * 2;
                float2 v;
                v.x = acc[mf][nf][half * 2 + 0] + __ldg(&bias[hbase + col]);
                v.y = acc[mf][nf][half * 2 + 1] + __ldg(&bias[hbase + col + 1]);
                *(float2*)(dst + col) = v;
            }
        }
    }
}

// ---------------- persistent LSTM recurrence ---------------------------------
// fp16 2-term; h exchanged as fp16 hi/lo; pre[t+1] prefetched under barrier.
#define RW0 0
#define RA0 65536
#define RG0 131072
#define LSTM_SMEM (131072 + 32 * 33 * 4)

__global__ void __launch_bounds__(256, 1)
lstm_persist() {
    extern __shared__ char smx[];
    uint32_t sb = smem_u32(smx);
    float* sG = (float*)(smx + RG0);

    int tid = threadIdx.x;
    int bx  = blockIdx.x;
    int lane = tid & 31;
    int wid  = tid >> 5;
    int grp2 = bx >> 6;
    int b0 = grp2 * 32;
    int colgrp = bx & 63;
    int h0 = colgrp * 8;
    int c0 = colgrp * 32;

    // ---- load W' slice once: 32 cols x 1024 fp16, 16 chunks, swizzled
    for (int v = tid; v < 32 * 128; v += 256) {
        int r = v >> 7;
        int g8 = v & 127;
        uint4 w = *(const uint4*)(g_Wcat + (size_t)(c0 + r) * 1024 + g8 * 8);
        int chunk = g8 >> 3;
        uint32_t off = SW128(r * 128 + (g8 & 7) * 16);
        *(uint4*)(smx + RW0 + chunk * 4096 + off) = w;
    }

    // zero h buffer 0 (one cell per thread chip-wide)
    g_hHI[0][bx * 256 + tid] = __float2half(0.f);
    g_hLO[0][bx * 256 + tid] = __float2half(0.f);

    int mhalf = wid & 1;
    int nq = wid >> 1;
    int bl = tid >> 3;
    int phl = tid & 7;
    float c_reg = 0.f;

    // prefetch pre[0]
    const float* pre0 = g_pre;
    float pf = __ldcg(&pre0[((0 * 64) + b0 + bl) * HH + h0 + phl]);
    float pi = __ldcg(&pre0[((1 * 64) + b0 + bl) * HH + h0 + phl]);
    float pg = __ldcg(&pre0[((2 * 64) + b0 + bl) * HH + h0 + phl]);
    float po = __ldcg(&pre0[((3 * 64) + b0 + bl) * HH + h0 + phl]);

    // initial barrier (full arrive+wait)
    {
        __threadfence();
        __syncthreads();
        if (tid == 0) {
            unsigned gen = *((volatile unsigned*)&g_gen2[grp2]);
            if (atomicAdd(&g_count2[grp2], 1u) == 63) {
                g_count2[grp2] = 0;
                __threadfence();
                *((volatile unsigned*)&g_gen2[grp2]) = gen + 1;
            } else {
                while (*((volatile unsigned*)&g_gen2[grp2]) == gen) { }
            }
        }
        __syncthreads();
    }

    int arow = mhalf * 16 + (lane & 15);
    int asel = lane >> 4;
    int lnq = lane & 15;
    int brow = nq * 8 + (lnq & 7);
    int bsel = (lnq >> 3) & 1;
    int rw = mhalf * 16 + (lane >> 2);
    int cw = nq * 8 + (lane & 3) * 2;

    for (int t = 0; t < TT; t++) {
        int buf = t & 1;
        // ---- stage A' = [Hh | Hl'] straight copies (no conversion)
        const __half* hHI = g_hHI[buf];
        const __half* hLO = g_hLO[buf];
        for (int v = tid; v < 2048; v += 256) {
            int r = v >> 6;
            int q = v & 63;
            uint4 hi = __ldcg((const uint4*)(hHI + (size_t)(b0 + r) * HH + q * 8));
            uint4 lo = __ldcg((const uint4*)(hLO + (size_t)(b0 + r) * HH + q * 8));
            int chunk = q >> 3;
            uint32_t off = SW128(r * 128 + (q & 7) * 16);
            *(uint4*)(smx + RA0 + chunk * 4096 + off) = hi;
            *(uint4*)(smx + RA0 + (chunk + 8) * 4096 + off) = lo;
        }
        __syncthreads();

        // ---- gates mma: K' = 1024 (seg0 Hh, seg1 Hl'; W repeats)
        float acc[4] = {0.f, 0.f, 0.f, 0.f};
        #pragma unroll 4
        for (int kk16 = 0; kk16 < 32; kk16++) {
            int chunk = kk16 >> 2;
            int kb = (kk16 & 3) * 32;
            uint32_t a[4], b2[2];
            ldsm4(a, sb + RA0 + chunk * 4096 + SW128(arow * 128 + kb + asel * 16));
            ldsm2(b2, sb + RW0 + chunk * 4096 + SW128(brow * 128 + kb + bsel * 16));
            mma_f16(acc, a, b2);
        }
        #pragma unroll
        for (int e = 0; e < 4; e++) acc[e] *= LO_SCALE;
        #pragma unroll 4
        for (int kk16 = 32; kk16 < 64; kk16++) {
            int chunk = kk16 >> 2;          // 8..15 (A' lo seg)
            int wchunk = (kk16 - 32) >> 2;  // W repeats seg0
            int kb = (kk16 & 3) * 32;
            uint32_t a[4], b2[2];
            ldsm4(a, sb + RA0 + chunk * 4096 + SW128(arow * 128 + kb + asel * 16));
            ldsm2(b2, sb + RW0 + wchunk * 4096 + SW128(brow * 128 + kb + bsel * 16));
            mma_f16(acc, a, b2);
        }
        sG[rw * 33 + cw]           = acc[0] * LO_INV;
        sG[rw * 33 + cw + 1]       = acc[1] * LO_INV;
        sG[(rw + 8) * 33 + cw]     = acc[2] * LO_INV;
        sG[(rw + 8) * 33 + cw + 1] = acc[3] * LO_INV;
        __syncthreads();

        // ---- cell update
        float gf = pf + sG[bl * 33 + phl * 4 + 0];
        float gi = pi + sG[bl * 33 + phl * 4 + 1];
        float gg = pg + sG[bl * 33 + phl * 4 + 2];
        float go = po + sG[bl * 33 + phl * 4 + 3];
        float f  = sigm_f(gf);
        float i  = sigm_f(gi);
        float g  = tanh_f(gg);
        float o  = sigm_f(go);
        c_reg = f * c_reg + i * g;
        float hnew = o * tanh_f(c_reg);
        // store hi/lo fp16 split
        int hoff = (b0 + bl) * HH + h0 + phl;
        __half hh = __float2half(hnew);
        __half hl = __float2half((hnew - __half2float(hh)) * LO_SCALE);
        g_hHI[buf ^ 1][hoff] = hh;
        g_hLO[buf ^ 1][hoff] = hl;
        if (t == TT - 1) {
            g_hfinal[hoff] = hnew;
            g_c[hoff] = c_reg;
        }

        // ---- barrier arrive
        __threadfence();
        __syncthreads();
        unsigned gen_snap = 0;
        if (tid == 0) {
            gen_snap = *((volatile unsigned*)&g_gen2[grp2]);
            if (atomicAdd(&g_count2[grp2], 1u) == 63) {
                g_count2[grp2] = 0;
                __threadfence();
                *((volatile unsigned*)&g_gen2[grp2]) = gen_snap + 1;
            }
        }
        // ---- prefetch pre[t+1] under the barrier wait
        int tn = (t + 1 < TT) ? t + 1 : t;
        const float* pre_n = g_pre + (size_t)tn * 4 * BB * HH;
        pf = __ldcg(&pre_n[((0 * 64) + b0 + bl) * HH + h0 + phl]);
        pi = __ldcg(&pre_n[((1 * 64) + b0 + bl) * HH + h0 + phl]);
        pg = __ldcg(&pre_n[((2 * 64) + b0 + bl) * HH + h0 + phl]);
        po = __ldcg(&pre_n[((3 * 64) + b0 + bl) * HH + h0 + phl]);
        // ---- barrier wait
        if (tid == 0) {
            while (*((volatile unsigned*)&g_gen2[grp2]) == gen_snap) { }
        }
        __syncthreads();
    }
}

// ---------------- final: out = h @ W_lin + b_lin; emit (out, h, c) ----------
__global__ void final_k(const float* __restrict__ Wlin, const float* __restrict__ blin,
                        float* __restrict__ out) {
    int b = blockIdx.x;
    int tid = threadIdx.x;
    const float* h = g_hfinal;
    const float* c = g_c;

    float* out_h = out + BB * OO;
    float* out_c = out + BB * OO + BB * HH;
    for (int v = tid; v < HH; v += 256) {
        out_h[b * HH + v] = h[b * HH + v];
        out_c[b * HH + v] = c[b * HH + v];
    }
    __shared__ float red[256 * OO];
    float p[OO];
    #pragma unroll
    for (int o = 0; o < OO; o++) p[o] = 0.f;
    for (int k = tid; k < HH; k += 256) {
        float hv = h[b * HH + k];
        #pragma unroll
        for (int o = 0; o < OO; o++) p[o] += hv * Wlin[k * OO + o];
    }
    #pragma unroll
    for (int o = 0; o < OO; o++) red[tid * OO + o] = p[o];
    __syncthreads();
    for (int s = 128; s > 0; s >>= 1) {
        if (tid < s)
            #pragma unroll
            for (int o = 0; o < OO; o++) red[tid * OO + o] += red[(tid + s) * OO + o];
        __syncthreads();
    }
    if (tid < OO) out[b * OO + tid] = red[tid] + blin[tid];
}

// ---------------- host launcher ---------------------------------------------
extern "C" void kernel_launch(void* const* d_in, const int* in_sizes, int n_in,
                              void* d_out, int out_size) {
    const int*   x    = (const int*)d_in[0];
    const float* emb  = (const float*)d_in[1];
    const float* Wfx  = (const float*)d_in[2];
    const float* Wfh  = (const float*)d_in[3];
    const float* bfp  = (const float*)d_in[4];
    const float* Wix  = (const float*)d_in[5];
    const float* Wih  = (const float*)d_in[6];
    const float* bip  = (const float*)d_in[7];
    const float* Wgx  = (const float*)d_in[8];
    const float* Wgh  = (const float*)d_in[9];
    const float* bgp  = (const float*)d_in[10];
    const float* Wox  = (const float*)d_in[11];
    const float* Woh  = (const float*)d_in[12];
    const float* bop  = (const float*)d_in[13];
    const float* Wlin = (const float*)d_in[14];
    const float* blin = (const float*)d_in[15];
    float* out = (float*)d_out;

    cudaFuncSetAttribute(mma_gemm, cudaFuncAttributeMaxDynamicSharedMemorySize, GEMM_SMEM);
    cudaFuncSetAttribute(lstm_persist, cudaFuncAttributeMaxDynamicSharedMemorySize, LSTM_SMEM);

    prep_A<<<65536, 256>>>(x, emb);
    prep_B<<<dim3(KK / 32, NT / 32), dim3(32, 32)>>>(Wfx, Wix, Wgx, Wox);
    prep_Wcat<<<NT * 4, 256>>>(Wfh, Wih, Wgh, Woh);
    mma_gemm<<<dim3(NT / 128, MM / 128), 256, GEMM_SMEM>>>(bfp, bip, bgp, bop);
    lstm_persist<<<NBLK, 256, LSTM_SMEM>>>();
    final_k<<<BB, 256>>>(Wlin, blin, out);
}